// round 10
// baseline (speedup 1.0000x reference)
#include <cuda_runtime.h>

#define NMAX 100000
#define EMAX 3200000

typedef unsigned long long u64;

// scratch (all __device__ globals; no allocation anywhere)
__device__ int    g_degi  [NMAX];
__device__ int    g_rowptr[NMAX + 1];
__device__ int    g_next  [NMAX];
__device__ int    g_bsum  [128];
__device__ int    g_ssrc  [EMAX];     // src ids sorted by dst (CSR adjacency)
__device__ float  g_dis   [NMAX];
__device__ float4 g_y     [NMAX * 4]; // dis * x1hat  (layer-1 message)
__device__ float4 g_y2    [NMAX * 4]; // dis * x2hat  (layer-2 message)
__device__ float4 g_AS    [NMAX * 8]; // per node: [0..3]=A1, [4..7]=A2 (one 128B line)
__device__ float4 g_BS    [NMAX * 8]; // per node: [0..3]=B1, [4..7]=B2

__device__ __forceinline__ float relu(float v) { return fmaxf(v, 0.0f); }

__device__ __forceinline__ u64 pack2(float lo, float hi) {
    u64 r; asm("mov.b64 %0, {%1, %2};" : "=l"(r) : "f"(lo), "f"(hi)); return r;
}
__device__ __forceinline__ u64 ffma2(u64 a, u64 b, u64 c) {
    u64 d; asm("fma.rn.f32x2 %0, %1, %2, %3;" : "=l"(d) : "l"(a), "l"(b), "l"(c)); return d;
}
__device__ __forceinline__ float2 unpack2(u64 v) {
    float2 f; asm("mov.b64 {%0, %1}, %2;" : "=f"(f.x), "=f"(f.y) : "l"(v)); return f;
}

// ---------------------------------------------------------------- degree
__global__ void k_deg(const int* __restrict__ ei, int E) {
    int e = blockIdx.x * blockDim.x + threadIdx.x;
    if (e < E) atomicAdd(&g_degi[ei[(size_t)E + e]], 1);
}

// -------------------------------------------- per-1024-chunk block sums
__global__ void k_bsum(int N) {              // grid = NB, block = 1024
    int i = blockIdx.x * 1024 + threadIdx.x;
    int v = (i < N) ? g_degi[i] : 0;
#pragma unroll
    for (int o = 16; o; o >>= 1) v += __shfl_down_sync(0xFFFFFFFFu, v, o);
    __shared__ int ws[32];
    if ((threadIdx.x & 31) == 0) ws[threadIdx.x >> 5] = v;
    __syncthreads();
    if (threadIdx.x < 32) {
        int u = ws[threadIdx.x];
#pragma unroll
        for (int o = 16; o; o >>= 1) u += __shfl_down_sync(0xFFFFFFFFu, u, o);
        if (threadIdx.x == 0) g_bsum[blockIdx.x] = u;
    }
}

// ---------- rowptr: block base = reduce(bsum[0..bid)), then local scan
__global__ void k_rowptr2(int N, int E) {    // grid = NB, block = 1024
    __shared__ int s[1024];
    __shared__ int ws[32];
    __shared__ int sbase;
    int t = threadIdx.x;

    int v = (t < blockIdx.x) ? g_bsum[t] : 0;   // NB <= 128
#pragma unroll
    for (int o = 16; o; o >>= 1) v += __shfl_down_sync(0xFFFFFFFFu, v, o);
    if ((t & 31) == 0) ws[t >> 5] = v;
    __syncthreads();
    if (t < 32) {
        int u = ws[t];
#pragma unroll
        for (int o = 16; o; o >>= 1) u += __shfl_down_sync(0xFFFFFFFFu, u, o);
        if (t == 0) sbase = u;
    }

    int i = blockIdx.x * 1024 + t;
    int d = (i < N) ? g_degi[i] : 0;
    s[t] = d;
    __syncthreads();
    for (int off = 1; off < 1024; off <<= 1) {
        int u = (t >= off) ? s[t - off] : 0;
        __syncthreads();
        s[t] += u;
        __syncthreads();
    }
    if (i < N) {
        int excl = sbase + s[t] - d;
        g_rowptr[i] = excl;
        g_next[i]   = excl;
    }
    if (blockIdx.x == 0 && t == 0) g_rowptr[N] = E;
}

// ------------------------------- scatter into CSR (src only, 4B store)
__global__ void k_scatter(const int* __restrict__ ei, int E) {
    int e = blockIdx.x * blockDim.x + threadIdx.x;
    if (e >= E) return;
    int src = ei[e];
    int dst = ei[(size_t)E + e];
    int pos = atomicAdd(&g_next[dst], 1);
    g_ssrc[pos] = src;
}

// ------------------------------------------------- node precompute layer 1
__global__ void k_node1(const float* __restrict__ x,
                        const float* __restrict__ wn1, const float* __restrict__ bn1,
                        const float* __restrict__ we1, int N) {
    __shared__ float swn[48], sbn[16], sA[256], sB[256];
    for (int i = threadIdx.x; i < 48; i += blockDim.x) swn[i] = wn1[i];
    for (int i = threadIdx.x; i < 16; i += blockDim.x) sbn[i] = bn1[i];
    for (int i = threadIdx.x; i < 256; i += blockDim.x) {
        sA[i] = we1[i];            // rows 0..15  (x_src part)
        sB[i] = we1[304 + i];      // rows 19..34 (x_dst part)
    }
    __syncthreads();
    int n = blockIdx.x * blockDim.x + threadIdx.x;
    if (n >= N) return;

    float x0 = x[(size_t)n*3], x1 = x[(size_t)n*3+1], x2 = x[(size_t)n*3+2];
    float dis = rsqrtf((float)g_degi[n]);
    g_dis[n] = dis;

    float h[16];
#pragma unroll
    for (int k = 0; k < 16; k++)
        h[k] = sbn[k] + x0*swn[k] + x1*swn[16+k] + x2*swn[32+k];

    float4* Y = &g_y[(size_t)n*4];
#pragma unroll
    for (int q = 0; q < 4; q++)
        Y[q] = make_float4(dis*h[4*q], dis*h[4*q+1], dis*h[4*q+2], dis*h[4*q+3]);

    float a[16], b[16];
#pragma unroll
    for (int k = 0; k < 16; k++) { a[k] = 0.f; b[k] = 0.f; }
#pragma unroll
    for (int j = 0; j < 16; j++)
#pragma unroll
        for (int k = 0; k < 16; k++) {
            a[k] += h[j] * sA[j*16+k];
            b[k] += h[j] * sB[j*16+k];
        }
    float4* A = &g_AS[(size_t)n*8];      // A1 slots 0..3
    float4* B = &g_BS[(size_t)n*8];      // B1 slots 0..3
#pragma unroll
    for (int q = 0; q < 4; q++) {
        A[q] = make_float4(a[4*q], a[4*q+1], a[4*q+2], a[4*q+3]);
        B[q] = make_float4(b[4*q], b[4*q+1], b[4*q+2], b[4*q+3]);
    }
}

// ---------- fused: quad CSR-gather aggregation (layer1) + node2 transform
__global__ void k_agg_node2(const float* __restrict__ wn2, const float* __restrict__ bn2,
                            const float* __restrict__ we2, int N) {
    __shared__ float sw[256], sbn[16], sA[256], sB[256];
    __shared__ float sagg[64 * 17];
    for (int i = threadIdx.x; i < 16; i += blockDim.x) sbn[i] = bn2[i];
    for (int i = threadIdx.x; i < 256; i += blockDim.x) {
        sw[i] = wn2[i];
        sA[i] = we2[i];
        sB[i] = we2[512 + i];
    }
    __syncthreads();

    int t = threadIdx.x;
    int lane = t & 3, q = t >> 2;
    int n = blockIdx.x * 64 + q;

    float4 acc = make_float4(0.f, 0.f, 0.f, 0.f);
    if (n < N) {
        int s  = g_rowptr[n];
        int en = g_rowptr[n + 1];
#pragma unroll 4
        for (int p = s; p < en; p++) {
            int src = g_ssrc[p];
            float4 v = g_y[(size_t)src * 4 + lane];
            acc.x += v.x; acc.y += v.y; acc.z += v.z; acc.w += v.w;
        }
    }
    float* sg = &sagg[q * 17 + lane * 4];
    sg[0] = acc.x; sg[1] = acc.y; sg[2] = acc.z; sg[3] = acc.w;
    __syncthreads();

    if (t >= 64) return;
    int n2 = blockIdx.x * 64 + t;
    if (n2 >= N) return;

    float dis = g_dis[n2];
    const float* ag = &sagg[t * 17];
    float h[16];
#pragma unroll
    for (int k = 0; k < 16; k++) h[k] = relu(dis * ag[k]);

    float v[16];
#pragma unroll
    for (int k = 0; k < 16; k++) v[k] = sbn[k];
#pragma unroll
    for (int j = 0; j < 16; j++)
#pragma unroll
        for (int k = 0; k < 16; k++) v[k] += h[j] * sw[j*16+k];

    float4* Y = &g_y2[(size_t)n2*4];
#pragma unroll
    for (int qq = 0; qq < 4; qq++)
        Y[qq] = make_float4(dis*v[4*qq], dis*v[4*qq+1], dis*v[4*qq+2], dis*v[4*qq+3]);

    float a[16], b[16];
#pragma unroll
    for (int k = 0; k < 16; k++) { a[k] = 0.f; b[k] = 0.f; }
#pragma unroll
    for (int j = 0; j < 16; j++)
#pragma unroll
        for (int k = 0; k < 16; k++) {
            a[k] += v[j] * sA[j*16+k];
            b[k] += v[j] * sB[j*16+k];
        }
    float4* A = &g_AS[(size_t)n2*8 + 4];   // A2 slots 4..7
    float4* B = &g_BS[(size_t)n2*8 + 4];   // B2 slots 4..7
#pragma unroll
    for (int qq = 0; qq < 4; qq++) {
        A[qq] = make_float4(a[4*qq], a[4*qq+1], a[4*qq+2], a[4*qq+3]);
        B[qq] = make_float4(b[4*qq], b[4*qq+1], b[4*qq+2], b[4*qq+3]);
    }
}

// ---------- fused: quad CSR-gather aggregation (layer2) + node output MLP
__global__ void k_agg_node3(const float* __restrict__ wnn1, const float* __restrict__ bnn1,
                            const float* __restrict__ wnn2, const float* __restrict__ bnn2,
                            float* __restrict__ out_node, int N) {
    __shared__ float sw1[256], sb1[16], sw2[48], sb2[3];
    __shared__ float sagg[64 * 17];
    for (int i = threadIdx.x; i < 256; i += blockDim.x) sw1[i] = wnn1[i];
    for (int i = threadIdx.x; i < 48;  i += blockDim.x) sw2[i] = wnn2[i];
    for (int i = threadIdx.x; i < 16;  i += blockDim.x) sb1[i] = bnn1[i];
    if (threadIdx.x < 3) sb2[threadIdx.x] = bnn2[threadIdx.x];
    __syncthreads();

    int t = threadIdx.x;
    int lane = t & 3, q = t >> 2;
    int n = blockIdx.x * 64 + q;

    float4 acc = make_float4(0.f, 0.f, 0.f, 0.f);
    if (n < N) {
        int s  = g_rowptr[n];
        int en = g_rowptr[n + 1];
#pragma unroll 4
        for (int p = s; p < en; p++) {
            int src = g_ssrc[p];
            float4 v = g_y2[(size_t)src * 4 + lane];
            acc.x += v.x; acc.y += v.y; acc.z += v.z; acc.w += v.w;
        }
    }
    float* sg = &sagg[q * 17 + lane * 4];
    sg[0] = acc.x; sg[1] = acc.y; sg[2] = acc.z; sg[3] = acc.w;
    __syncthreads();

    if (t >= 64) return;
    int n2 = blockIdx.x * 64 + t;
    if (n2 >= N) return;

    float dis = g_dis[n2];
    const float* ag = &sagg[t * 17];
    float h[16];
#pragma unroll
    for (int k = 0; k < 16; k++) h[k] = relu(dis * ag[k]);

    float tv[16];
#pragma unroll
    for (int k = 0; k < 16; k++) tv[k] = sb1[k];
#pragma unroll
    for (int j = 0; j < 16; j++)
#pragma unroll
        for (int k = 0; k < 16; k++) tv[k] += h[j] * sw1[j*16+k];

    float o0 = sb2[0], o1 = sb2[1], o2 = sb2[2];
#pragma unroll
    for (int j = 0; j < 16; j++) {
        float tj = relu(tv[j]);
        o0 += tj * sw2[j*3    ];
        o1 += tj * sw2[j*3 + 1];
        o2 += tj * sw2[j*3 + 2];
    }
    out_node[(size_t)n2*3    ] = o0;
    out_node[(size_t)n2*3 + 1] = o1;
    out_node[(size_t)n2*3 + 2] = o2;
}

// ------- layer-2 edge kernel, eid-order (coalesced ei/ea/out), packed A/B
__global__ void k_edge2(const int* __restrict__ ei, const float* __restrict__ ea,
                        const float* __restrict__ we1, const float* __restrict__ be1,
                        const float* __restrict__ we2, const float* __restrict__ be2,
                        const float* __restrict__ wen1, const float* __restrict__ ben1,
                        const float* __restrict__ wen2, const float* __restrict__ ben2,
                        float* __restrict__ out_edge, int E) {
    __shared__ float sm1[48], sbe1[16], sbe2[16], sb1[16], sw2[48], sb2[3];
    __shared__ __align__(16) float sm2[256];
    __shared__ __align__(16) float sw1[256];
    for (int i = threadIdx.x; i < 48; i += blockDim.x) {
        sm1[i] = we1[256 + i];     // w_e1 rows 16..18 (edge_attr part)
        sw2[i] = wen2[i];
    }
    for (int i = threadIdx.x; i < 256; i += blockDim.x) {
        sm2[i] = we2[256 + i];     // w_e2 rows 16..31 (edge part)
        sw1[i] = wen1[i];
    }
    for (int i = threadIdx.x; i < 16; i += blockDim.x) {
        sbe1[i] = be1[i]; sbe2[i] = be2[i]; sb1[i] = ben1[i];
    }
    if (threadIdx.x < 3) sb2[threadIdx.x] = ben2[threadIdx.x];
    __syncthreads();

    int e = blockIdx.x * blockDim.x + threadIdx.x;
    if (e >= E) return;
    int src = ei[e];                  // coalesced
    int dst = ei[(size_t)E + e];      // coalesced

    const float4* AS = &g_AS[(size_t)src*8];   // one random 128B line
    const float4* BS = &g_BS[(size_t)dst*8];   // one random 128B line

    float ea0 = ea[(size_t)e*3], ea1 = ea[(size_t)e*3+1], ea2 = ea[(size_t)e*3+2]; // coalesced

    // e1 = relu(A1[src] + ea@w_mid1 + B1[dst] + b_e1)
    float e1v[16];
#pragma unroll
    for (int q = 0; q < 4; q++) {
        float4 ta = AS[q], tb = BS[q];
        float s0 = ta.x + tb.x, s1 = ta.y + tb.y, s2 = ta.z + tb.z, s3 = ta.w + tb.w;
        int k = 4*q;
        e1v[k  ] = relu(s0 + sbe1[k  ] + ea0*sm1[k  ] + ea1*sm1[16+k  ] + ea2*sm1[32+k  ]);
        e1v[k+1] = relu(s1 + sbe1[k+1] + ea0*sm1[k+1] + ea1*sm1[16+k+1] + ea2*sm1[32+k+1]);
        e1v[k+2] = relu(s2 + sbe1[k+2] + ea0*sm1[k+2] + ea1*sm1[16+k+2] + ea2*sm1[32+k+2]);
        e1v[k+3] = relu(s3 + sbe1[k+3] + ea0*sm1[k+3] + ea1*sm1[16+k+3] + ea2*sm1[32+k+3]);
    }

    // e2 = relu(A2[src] + B2[dst] + be2 + e1 @ sm2)   [f32x2]
    float e2v[16];
    {
        u64 acc[8];
#pragma unroll
        for (int q = 0; q < 4; q++) {
            float4 ta = AS[4+q], tb = BS[4+q];
            acc[2*q  ] = pack2(ta.x + tb.x + sbe2[4*q  ], ta.y + tb.y + sbe2[4*q+1]);
            acc[2*q+1] = pack2(ta.z + tb.z + sbe2[4*q+2], ta.w + tb.w + sbe2[4*q+3]);
        }
        const u64* W = (const u64*)sm2;
#pragma unroll
        for (int j = 0; j < 16; j++) {
            u64 ej = pack2(e1v[j], e1v[j]);
#pragma unroll
            for (int kk = 0; kk < 8; kk++)
                acc[kk] = ffma2(ej, W[j*8 + kk], acc[kk]);
        }
#pragma unroll
        for (int kk = 0; kk < 8; kk++) {
            float2 f = unpack2(acc[kk]);
            e2v[2*kk  ] = relu(f.x);
            e2v[2*kk+1] = relu(f.y);
        }
    }

    // t = e2 @ wen1 + b    [f32x2]
    float tvv[16];
    {
        u64 acc[8];
#pragma unroll
        for (int kk = 0; kk < 8; kk++) acc[kk] = pack2(sb1[2*kk], sb1[2*kk+1]);
        const u64* W = (const u64*)sw1;
#pragma unroll
        for (int j = 0; j < 16; j++) {
            u64 ej = pack2(e2v[j], e2v[j]);
#pragma unroll
            for (int kk = 0; kk < 8; kk++)
                acc[kk] = ffma2(ej, W[j*8 + kk], acc[kk]);
        }
#pragma unroll
        for (int kk = 0; kk < 8; kk++) {
            float2 f = unpack2(acc[kk]);
            tvv[2*kk  ] = f.x;
            tvv[2*kk+1] = f.y;
        }
    }

    float o0 = sb2[0], o1 = sb2[1], o2 = sb2[2];
#pragma unroll
    for (int j = 0; j < 16; j++) {
        float tj = relu(tvv[j]);
        o0 += tj * sw2[j*3    ];
        o1 += tj * sw2[j*3 + 1];
        o2 += tj * sw2[j*3 + 2];
    }
    out_edge[(size_t)e*3    ] = o0;   // coalesced
    out_edge[(size_t)e*3 + 1] = o1;
    out_edge[(size_t)e*3 + 2] = o2;
}

extern "C" void kernel_launch(void* const* d_in, const int* in_sizes, int n_in,
                              void* d_out, int out_size) {
    const float* x    = (const float*)d_in[0];
    const float* ea   = (const float*)d_in[1];
    const int*   ei   = (const int*)d_in[2];      // int32 (JAX x64 disabled)
    const float *wn1 = (const float*)d_in[3],  *bn1 = (const float*)d_in[4];
    const float *we1 = (const float*)d_in[5],  *be1 = (const float*)d_in[6];
    const float *wn2 = (const float*)d_in[7],  *bn2 = (const float*)d_in[8];
    const float *we2 = (const float*)d_in[9],  *be2 = (const float*)d_in[10];
    const float *wnn1= (const float*)d_in[11], *bnn1= (const float*)d_in[12];
    const float *wnn2= (const float*)d_in[13], *bnn2= (const float*)d_in[14];
    const float *wen1= (const float*)d_in[15], *ben1= (const float*)d_in[16];
    const float *wen2= (const float*)d_in[17], *ben2= (const float*)d_in[18];

    int N = in_sizes[0] / 3;
    int E = in_sizes[1] / 3;
    float* out_node = (float*)d_out;
    float* out_edge = out_node + (size_t)N * 3;

    void* pdegi;
    cudaGetSymbolAddress(&pdegi, g_degi);
    cudaMemsetAsync(pdegi, 0, (size_t)N * sizeof(int));

    const int TB = 256;
    int gbE   = (E + TB - 1) / TB;
    int gbN   = (N + TB - 1) / TB;
    int gbN64 = (N + 63) / 64;
    int NB    = (N + 1023) / 1024;

    k_deg      <<<gbE,  TB>>>(ei, E);            // launch 1
    k_bsum     <<<NB, 1024>>>(N);                // launch 2
    k_rowptr2  <<<NB, 1024>>>(N, E);             // launch 3
    k_scatter  <<<gbE,  TB>>>(ei, E);            // launch 4  <- profiled
    k_node1    <<<gbN,  TB>>>(x, wn1, bn1, we1, N);
    k_agg_node2<<<gbN64, TB>>>(wn2, bn2, we2, N);
    k_edge2    <<<gbE,  TB>>>(ei, ea, we1, be1, we2, be2, wen1, ben1, wen2, ben2,
                              out_edge, E);
    k_agg_node3<<<gbN64, TB>>>(wnn1, bnn1, wnn2, bnn2, out_node, N);
}

// round 11
// speedup vs baseline: 1.1393x; 1.1393x over previous
#include <cuda_runtime.h>

#define NMAX 100000
#define EMAX 3200000

typedef unsigned long long u64;

// scratch (all __device__ globals; no allocation anywhere)
__device__ int    g_degi  [NMAX];
__device__ int    g_rowptr[NMAX + 1];
__device__ int    g_next  [NMAX];
__device__ int    g_bsum  [128];
__device__ int4   g_sedge [EMAX];     // (src, eid, dst, 0) sorted by dst
__device__ float  g_dis   [NMAX];
__device__ float4 g_y     [NMAX * 4];
__device__ float4 g_y2    [NMAX * 4];
__device__ float4 g_A1    [NMAX * 4];
__device__ float4 g_B1    [NMAX * 4];
__device__ float4 g_A2    [NMAX * 4];
__device__ float4 g_B2    [NMAX * 4];

__device__ __forceinline__ float relu(float v) { return fmaxf(v, 0.0f); }

__device__ __forceinline__ u64 pack2(float lo, float hi) {
    u64 r; asm("mov.b64 %0, {%1, %2};" : "=l"(r) : "f"(lo), "f"(hi)); return r;
}
__device__ __forceinline__ u64 ffma2(u64 a, u64 b, u64 c) {
    u64 d; asm("fma.rn.f32x2 %0, %1, %2, %3;" : "=l"(d) : "l"(a), "l"(b), "l"(c)); return d;
}
__device__ __forceinline__ float2 unpack2(u64 v) {
    float2 f; asm("mov.b64 {%0, %1}, %2;" : "=f"(f.x), "=f"(f.y) : "l"(v)); return f;
}

// ---------------------------------------------------------------- degree
__global__ void k_deg(const int* __restrict__ ei, int E) {
    int e = blockIdx.x * blockDim.x + threadIdx.x;
    if (e < E) atomicAdd(&g_degi[ei[(size_t)E + e]], 1);
}

// -------------------------------------------- per-1024-chunk block sums
__global__ void k_bsum(int N) {
    int i = blockIdx.x * 1024 + threadIdx.x;
    int v = (i < N) ? g_degi[i] : 0;
#pragma unroll
    for (int o = 16; o; o >>= 1) v += __shfl_down_sync(0xFFFFFFFFu, v, o);
    __shared__ int ws[32];
    if ((threadIdx.x & 31) == 0) ws[threadIdx.x >> 5] = v;
    __syncthreads();
    if (threadIdx.x < 32) {
        int u = ws[threadIdx.x];
#pragma unroll
        for (int o = 16; o; o >>= 1) u += __shfl_down_sync(0xFFFFFFFFu, u, o);
        if (threadIdx.x == 0) g_bsum[blockIdx.x] = u;
    }
}

// ---------- rowptr: block base = reduce(bsum[0..bid)), then local scan
__global__ void k_rowptr2(int N, int E) {
    __shared__ int s[1024];
    __shared__ int ws[32];
    __shared__ int sbase;
    int t = threadIdx.x;

    int v = (t < blockIdx.x) ? g_bsum[t] : 0;
#pragma unroll
    for (int o = 16; o; o >>= 1) v += __shfl_down_sync(0xFFFFFFFFu, v, o);
    if ((t & 31) == 0) ws[t >> 5] = v;
    __syncthreads();
    if (t < 32) {
        int u = ws[t];
#pragma unroll
        for (int o = 16; o; o >>= 1) u += __shfl_down_sync(0xFFFFFFFFu, u, o);
        if (t == 0) sbase = u;
    }

    int i = blockIdx.x * 1024 + t;
    int d = (i < N) ? g_degi[i] : 0;
    s[t] = d;
    __syncthreads();
    for (int off = 1; off < 1024; off <<= 1) {
        int u = (t >= off) ? s[t - off] : 0;
        __syncthreads();
        s[t] += u;
        __syncthreads();
    }
    if (i < N) {
        int excl = sbase + s[t] - d;
        g_rowptr[i] = excl;
        g_next[i]   = excl;
    }
    if (blockIdx.x == 0 && t == 0) g_rowptr[N] = E;
}

// ----------------------------------------------------- scatter into CSR
__global__ void k_scatter(const int* __restrict__ ei, int E) {
    int e = blockIdx.x * blockDim.x + threadIdx.x;
    if (e >= E) return;
    int src = ei[e];
    int dst = ei[(size_t)E + e];
    int pos = atomicAdd(&g_next[dst], 1);
    g_sedge[pos] = make_int4(src, e, dst, 0);
}

// ------------------------------------------------- node precompute layer 1
__global__ void k_node1(const float* __restrict__ x,
                        const float* __restrict__ wn1, const float* __restrict__ bn1,
                        const float* __restrict__ we1, int N) {
    __shared__ float swn[48], sbn[16], sA[256], sB[256];
    for (int i = threadIdx.x; i < 48; i += blockDim.x) swn[i] = wn1[i];
    for (int i = threadIdx.x; i < 16; i += blockDim.x) sbn[i] = bn1[i];
    for (int i = threadIdx.x; i < 256; i += blockDim.x) {
        sA[i] = we1[i];
        sB[i] = we1[304 + i];
    }
    __syncthreads();
    int n = blockIdx.x * blockDim.x + threadIdx.x;
    if (n >= N) return;

    float x0 = x[(size_t)n*3], x1 = x[(size_t)n*3+1], x2 = x[(size_t)n*3+2];
    float dis = rsqrtf((float)g_degi[n]);
    g_dis[n] = dis;

    float h[16];
#pragma unroll
    for (int k = 0; k < 16; k++)
        h[k] = sbn[k] + x0*swn[k] + x1*swn[16+k] + x2*swn[32+k];

    float4* Y = &g_y[(size_t)n*4];
#pragma unroll
    for (int q = 0; q < 4; q++)
        Y[q] = make_float4(dis*h[4*q], dis*h[4*q+1], dis*h[4*q+2], dis*h[4*q+3]);

    float a[16], b[16];
#pragma unroll
    for (int k = 0; k < 16; k++) { a[k] = 0.f; b[k] = 0.f; }
#pragma unroll
    for (int j = 0; j < 16; j++)
#pragma unroll
        for (int k = 0; k < 16; k++) {
            a[k] += h[j] * sA[j*16+k];
            b[k] += h[j] * sB[j*16+k];
        }
    float4* A = &g_A1[(size_t)n*4];
    float4* B = &g_B1[(size_t)n*4];
#pragma unroll
    for (int q = 0; q < 4; q++) {
        A[q] = make_float4(a[4*q], a[4*q+1], a[4*q+2], a[4*q+3]);
        B[q] = make_float4(b[4*q], b[4*q+1], b[4*q+2], b[4*q+3]);
    }
}

// ---------- fused: quad CSR-gather aggregation (layer1) + node2 transform
__global__ void k_agg_node2(const float* __restrict__ wn2, const float* __restrict__ bn2,
                            const float* __restrict__ we2, int N) {
    __shared__ float sw[256], sbn[16], sA[256], sB[256];
    __shared__ float sagg[64 * 17];
    for (int i = threadIdx.x; i < 16; i += blockDim.x) sbn[i] = bn2[i];
    for (int i = threadIdx.x; i < 256; i += blockDim.x) {
        sw[i] = wn2[i];
        sA[i] = we2[i];
        sB[i] = we2[512 + i];
    }
    __syncthreads();

    int t = threadIdx.x;
    int lane = t & 3, q = t >> 2;
    int n = blockIdx.x * 64 + q;

    float4 acc = make_float4(0.f, 0.f, 0.f, 0.f);
    if (n < N) {
        int s  = g_rowptr[n];
        int en = g_rowptr[n + 1];
#pragma unroll 4
        for (int p = s; p < en; p++) {
            int src = g_sedge[p].x;
            float4 v = g_y[(size_t)src * 4 + lane];
            acc.x += v.x; acc.y += v.y; acc.z += v.z; acc.w += v.w;
        }
    }
    float* sg = &sagg[q * 17 + lane * 4];
    sg[0] = acc.x; sg[1] = acc.y; sg[2] = acc.z; sg[3] = acc.w;
    __syncthreads();

    if (t >= 64) return;
    int n2 = blockIdx.x * 64 + t;
    if (n2 >= N) return;

    float dis = g_dis[n2];
    const float* ag = &sagg[t * 17];
    float h[16];
#pragma unroll
    for (int k = 0; k < 16; k++) h[k] = relu(dis * ag[k]);

    float v[16];
#pragma unroll
    for (int k = 0; k < 16; k++) v[k] = sbn[k];
#pragma unroll
    for (int j = 0; j < 16; j++)
#pragma unroll
        for (int k = 0; k < 16; k++) v[k] += h[j] * sw[j*16+k];

    float4* Y = &g_y2[(size_t)n2*4];
#pragma unroll
    for (int qq = 0; qq < 4; qq++)
        Y[qq] = make_float4(dis*v[4*qq], dis*v[4*qq+1], dis*v[4*qq+2], dis*v[4*qq+3]);

    float a[16], b[16];
#pragma unroll
    for (int k = 0; k < 16; k++) { a[k] = 0.f; b[k] = 0.f; }
#pragma unroll
    for (int j = 0; j < 16; j++)
#pragma unroll
        for (int k = 0; k < 16; k++) {
            a[k] += v[j] * sA[j*16+k];
            b[k] += v[j] * sB[j*16+k];
        }
    float4* A = &g_A2[(size_t)n2*4];
    float4* B = &g_B2[(size_t)n2*4];
#pragma unroll
    for (int qq = 0; qq < 4; qq++) {
        A[qq] = make_float4(a[4*qq], a[4*qq+1], a[4*qq+2], a[4*qq+3]);
        B[qq] = make_float4(b[4*qq], b[4*qq+1], b[4*qq+2], b[4*qq+3]);
    }
}

// ---------- fused: quad CSR-gather aggregation (layer2) + node output MLP
__global__ void k_agg_node3(const float* __restrict__ wnn1, const float* __restrict__ bnn1,
                            const float* __restrict__ wnn2, const float* __restrict__ bnn2,
                            float* __restrict__ out_node, int N) {
    __shared__ float sw1[256], sb1[16], sw2[48], sb2[3];
    __shared__ float sagg[64 * 17];
    for (int i = threadIdx.x; i < 256; i += blockDim.x) sw1[i] = wnn1[i];
    for (int i = threadIdx.x; i < 48;  i += blockDim.x) sw2[i] = wnn2[i];
    for (int i = threadIdx.x; i < 16;  i += blockDim.x) sb1[i] = bnn1[i];
    if (threadIdx.x < 3) sb2[threadIdx.x] = bnn2[threadIdx.x];
    __syncthreads();

    int t = threadIdx.x;
    int lane = t & 3, q = t >> 2;
    int n = blockIdx.x * 64 + q;

    float4 acc = make_float4(0.f, 0.f, 0.f, 0.f);
    if (n < N) {
        int s  = g_rowptr[n];
        int en = g_rowptr[n + 1];
#pragma unroll 4
        for (int p = s; p < en; p++) {
            int src = g_sedge[p].x;
            float4 v = g_y2[(size_t)src * 4 + lane];
            acc.x += v.x; acc.y += v.y; acc.z += v.z; acc.w += v.w;
        }
    }
    float* sg = &sagg[q * 17 + lane * 4];
    sg[0] = acc.x; sg[1] = acc.y; sg[2] = acc.z; sg[3] = acc.w;
    __syncthreads();

    if (t >= 64) return;
    int n2 = blockIdx.x * 64 + t;
    if (n2 >= N) return;

    float dis = g_dis[n2];
    const float* ag = &sagg[t * 17];
    float h[16];
#pragma unroll
    for (int k = 0; k < 16; k++) h[k] = relu(dis * ag[k]);

    float tv[16];
#pragma unroll
    for (int k = 0; k < 16; k++) tv[k] = sb1[k];
#pragma unroll
    for (int j = 0; j < 16; j++)
#pragma unroll
        for (int k = 0; k < 16; k++) tv[k] += h[j] * sw1[j*16+k];

    float o0 = sb2[0], o1 = sb2[1], o2 = sb2[2];
#pragma unroll
    for (int j = 0; j < 16; j++) {
        float tj = relu(tv[j]);
        o0 += tj * sw2[j*3    ];
        o1 += tj * sw2[j*3 + 1];
        o2 += tj * sw2[j*3 + 2];
    }
    out_node[(size_t)n2*3    ] = o0;
    out_node[(size_t)n2*3 + 1] = o1;
    out_node[(size_t)n2*3 + 2] = o2;
}

// ------- layer-2 edge kernel, CSR order, TWO edges per thread
// (weight LDS loads amortized across both edges — halves per-edge LDS count)
__global__ void __launch_bounds__(256) k_edge2c(
                         const float* __restrict__ ea,
                         const float* __restrict__ we1, const float* __restrict__ be1,
                         const float* __restrict__ we2, const float* __restrict__ be2,
                         const float* __restrict__ wen1, const float* __restrict__ ben1,
                         const float* __restrict__ wen2, const float* __restrict__ ben2,
                         float* __restrict__ out_edge, int E) {
    __shared__ float sm1[48], sbe1[16], sbe2[16], sb1[16], sw2[48], sb2[3];
    __shared__ __align__(16) float sm2[256];
    __shared__ __align__(16) float sw1[256];
    for (int i = threadIdx.x; i < 48; i += blockDim.x) {
        sm1[i] = we1[256 + i];
        sw2[i] = wen2[i];
    }
    for (int i = threadIdx.x; i < 256; i += blockDim.x) {
        sm2[i] = we2[256 + i];
        sw1[i] = wen1[i];
    }
    for (int i = threadIdx.x; i < 16; i += blockDim.x) {
        sbe1[i] = be1[i]; sbe2[i] = be2[i]; sb1[i] = ben1[i];
    }
    if (threadIdx.x < 3) sb2[threadIdx.x] = ben2[threadIdx.x];
    __syncthreads();

    int base = blockIdx.x * 512;
    int p0 = base + threadIdx.x;
    int p1 = p0 + 256;
    bool v0 = p0 < E, v1 = p1 < E;
    int4 r0 = v0 ? g_sedge[p0] : make_int4(0, 0, 0, 0);
    int4 r1 = v1 ? g_sedge[p1] : make_int4(0, 0, 0, 0);

    float ea0a = ea[(size_t)r0.y*3], ea1a = ea[(size_t)r0.y*3+1], ea2a = ea[(size_t)r0.y*3+2];
    float ea0b = ea[(size_t)r1.y*3], ea1b = ea[(size_t)r1.y*3+1], ea2b = ea[(size_t)r1.y*3+2];

    // e1 for both edges
    float e1a[16], e1b[16];
    {
        const float4* Aa = &g_A1[(size_t)r0.x*4];
        const float4* Ba = &g_B1[(size_t)r0.z*4];
        const float4* Ab = &g_A1[(size_t)r1.x*4];
        const float4* Bb = &g_B1[(size_t)r1.z*4];
#pragma unroll
        for (int q = 0; q < 4; q++) {
            float4 ta = Aa[q], tb = Ba[q];
            float4 tc = Ab[q], td = Bb[q];
            int k = 4*q;
#pragma unroll
            for (int i = 0; i < 4; i++) {
                float wa = sm1[k+i], wb = sm1[16+k+i], wc = sm1[32+k+i], bb = sbe1[k+i];
                float sa = (i==0?ta.x:i==1?ta.y:i==2?ta.z:ta.w) + (i==0?tb.x:i==1?tb.y:i==2?tb.z:tb.w);
                float sb = (i==0?tc.x:i==1?tc.y:i==2?tc.z:tc.w) + (i==0?td.x:i==1?td.y:i==2?td.z:td.w);
                e1a[k+i] = relu(sa + bb + ea0a*wa + ea1a*wb + ea2a*wc);
                e1b[k+i] = relu(sb + bb + ea0b*wa + ea1b*wb + ea2b*wc);
            }
        }
    }

    // e2 for both edges (shared W loads)
    float e2a[16], e2b[16];
    {
        u64 acca[8], accb[8];
        const float4* Aa = &g_A2[(size_t)r0.x*4];
        const float4* Ba = &g_B2[(size_t)r0.z*4];
        const float4* Ab = &g_A2[(size_t)r1.x*4];
        const float4* Bb = &g_B2[(size_t)r1.z*4];
#pragma unroll
        for (int q = 0; q < 4; q++) {
            float4 ta = Aa[q], tb = Ba[q];
            float4 tc = Ab[q], td = Bb[q];
            acca[2*q  ] = pack2(ta.x + tb.x + sbe2[4*q  ], ta.y + tb.y + sbe2[4*q+1]);
            acca[2*q+1] = pack2(ta.z + tb.z + sbe2[4*q+2], ta.w + tb.w + sbe2[4*q+3]);
            accb[2*q  ] = pack2(tc.x + td.x + sbe2[4*q  ], tc.y + td.y + sbe2[4*q+1]);
            accb[2*q+1] = pack2(tc.z + td.z + sbe2[4*q+2], tc.w + td.w + sbe2[4*q+3]);
        }
        const u64* W = (const u64*)sm2;
#pragma unroll
        for (int j = 0; j < 16; j++) {
            u64 eja = pack2(e1a[j], e1a[j]);
            u64 ejb = pack2(e1b[j], e1b[j]);
#pragma unroll
            for (int kk = 0; kk < 8; kk++) {
                u64 w = W[j*8 + kk];
                acca[kk] = ffma2(eja, w, acca[kk]);
                accb[kk] = ffma2(ejb, w, accb[kk]);
            }
        }
#pragma unroll
        for (int kk = 0; kk < 8; kk++) {
            float2 fa = unpack2(acca[kk]);
            float2 fb = unpack2(accb[kk]);
            e2a[2*kk] = relu(fa.x); e2a[2*kk+1] = relu(fa.y);
            e2b[2*kk] = relu(fb.x); e2b[2*kk+1] = relu(fb.y);
        }
    }

    // t = e2 @ wen1 + b  (shared W loads)
    float tva[16], tvb[16];
    {
        u64 acca[8], accb[8];
#pragma unroll
        for (int kk = 0; kk < 8; kk++) {
            u64 b = pack2(sb1[2*kk], sb1[2*kk+1]);
            acca[kk] = b; accb[kk] = b;
        }
        const u64* W = (const u64*)sw1;
#pragma unroll
        for (int j = 0; j < 16; j++) {
            u64 eja = pack2(e2a[j], e2a[j]);
            u64 ejb = pack2(e2b[j], e2b[j]);
#pragma unroll
            for (int kk = 0; kk < 8; kk++) {
                u64 w = W[j*8 + kk];
                acca[kk] = ffma2(eja, w, acca[kk]);
                accb[kk] = ffma2(ejb, w, accb[kk]);
            }
        }
#pragma unroll
        for (int kk = 0; kk < 8; kk++) {
            float2 fa = unpack2(acca[kk]);
            float2 fb = unpack2(accb[kk]);
            tva[2*kk] = fa.x; tva[2*kk+1] = fa.y;
            tvb[2*kk] = fb.x; tvb[2*kk+1] = fb.y;
        }
    }

    float o0a = sb2[0], o1a = sb2[1], o2a = sb2[2];
    float o0b = sb2[0], o1b = sb2[1], o2b = sb2[2];
#pragma unroll
    for (int j = 0; j < 16; j++) {
        float w0 = sw2[j*3], w1 = sw2[j*3+1], w2 = sw2[j*3+2];
        float ta = relu(tva[j]);
        float tb = relu(tvb[j]);
        o0a += ta * w0; o1a += ta * w1; o2a += ta * w2;
        o0b += tb * w0; o1b += tb * w1; o2b += tb * w2;
    }
    if (v0) {
        out_edge[(size_t)r0.y*3    ] = o0a;
        out_edge[(size_t)r0.y*3 + 1] = o1a;
        out_edge[(size_t)r0.y*3 + 2] = o2a;
    }
    if (v1) {
        out_edge[(size_t)r1.y*3    ] = o0b;
        out_edge[(size_t)r1.y*3 + 1] = o1b;
        out_edge[(size_t)r1.y*3 + 2] = o2b;
    }
}

extern "C" void kernel_launch(void* const* d_in, const int* in_sizes, int n_in,
                              void* d_out, int out_size) {
    const float* x    = (const float*)d_in[0];
    const float* ea   = (const float*)d_in[1];
    const int*   ei   = (const int*)d_in[2];      // int32 (JAX x64 disabled)
    const float *wn1 = (const float*)d_in[3],  *bn1 = (const float*)d_in[4];
    const float *we1 = (const float*)d_in[5],  *be1 = (const float*)d_in[6];
    const float *wn2 = (const float*)d_in[7],  *bn2 = (const float*)d_in[8];
    const float *we2 = (const float*)d_in[9],  *be2 = (const float*)d_in[10];
    const float *wnn1= (const float*)d_in[11], *bnn1= (const float*)d_in[12];
    const float *wnn2= (const float*)d_in[13], *bnn2= (const float*)d_in[14];
    const float *wen1= (const float*)d_in[15], *ben1= (const float*)d_in[16];
    const float *wen2= (const float*)d_in[17], *ben2= (const float*)d_in[18];

    int N = in_sizes[0] / 3;
    int E = in_sizes[1] / 3;
    float* out_node = (float*)d_out;
    float* out_edge = out_node + (size_t)N * 3;

    void* pdegi;
    cudaGetSymbolAddress(&pdegi, g_degi);
    cudaMemsetAsync(pdegi, 0, (size_t)N * sizeof(int));

    const int TB = 256;
    int gbE   = (E + TB - 1) / TB;
    int gbE2  = (E + 511) / 512;
    int gbN   = (N + TB - 1) / TB;
    int gbN64 = (N + 63) / 64;
    int NB    = (N + 1023) / 1024;

    k_deg      <<<gbE,  TB>>>(ei, E);
    k_bsum     <<<NB, 1024>>>(N);
    k_rowptr2  <<<NB, 1024>>>(N, E);
    k_scatter  <<<gbE,  TB>>>(ei, E);            // slot 4 (profiled)
    k_node1    <<<gbN,  TB>>>(x, wn1, bn1, we1, N);
    k_agg_node2<<<gbN64, TB>>>(wn2, bn2, we2, N);
    k_edge2c   <<<gbE2, TB>>>(ea, we1, be1, we2, be2, wen1, ben1, wen2, ben2,
                              out_edge, E);
    k_agg_node3<<<gbN64, TB>>>(wnn1, bnn1, wnn2, bnn2, out_node, N);
}

// round 12
// speedup vs baseline: 1.1712x; 1.0280x over previous
#include <cuda_runtime.h>

#define NMAX 100000
#define EMAX 3200000

typedef unsigned long long u64;

// scratch (all __device__ globals; no allocation anywhere)
__device__ int    g_degi  [NMAX];
__device__ int    g_rowptr[NMAX + 1];
__device__ int    g_next  [NMAX];
__device__ int    g_bsum  [128];
__device__ int4   g_sedge [EMAX];     // (src, eid, dst, 0) sorted by dst
__device__ float  g_dis   [NMAX];
__device__ float4 g_y     [NMAX * 4];
__device__ float4 g_y2    [NMAX * 4];
__device__ float4 g_A1    [NMAX * 4];
__device__ float4 g_B1    [NMAX * 4];
__device__ float4 g_A2    [NMAX * 4];
__device__ float4 g_B2    [NMAX * 4];

__device__ __forceinline__ float relu(float v) { return fmaxf(v, 0.0f); }

__device__ __forceinline__ u64 pack2(float lo, float hi) {
    u64 r; asm("mov.b64 %0, {%1, %2};" : "=l"(r) : "f"(lo), "f"(hi)); return r;
}
__device__ __forceinline__ u64 ffma2(u64 a, u64 b, u64 c) {
    u64 d; asm("fma.rn.f32x2 %0, %1, %2, %3;" : "=l"(d) : "l"(a), "l"(b), "l"(c)); return d;
}
__device__ __forceinline__ float2 unpack2(u64 v) {
    float2 f; asm("mov.b64 {%0, %1}, %2;" : "=f"(f.x), "=f"(f.y) : "l"(v)); return f;
}

// ---------------------------------------------------------------- degree
__global__ void k_deg(const int* __restrict__ ei, int E) {
    int e = blockIdx.x * blockDim.x + threadIdx.x;
    if (e < E) atomicAdd(&g_degi[ei[(size_t)E + e]], 1);
}

// -------------------------------------------- per-1024-chunk block sums
__global__ void k_bsum(int N) {
    int i = blockIdx.x * 1024 + threadIdx.x;
    int v = (i < N) ? g_degi[i] : 0;
#pragma unroll
    for (int o = 16; o; o >>= 1) v += __shfl_down_sync(0xFFFFFFFFu, v, o);
    __shared__ int ws[32];
    if ((threadIdx.x & 31) == 0) ws[threadIdx.x >> 5] = v;
    __syncthreads();
    if (threadIdx.x < 32) {
        int u = ws[threadIdx.x];
#pragma unroll
        for (int o = 16; o; o >>= 1) u += __shfl_down_sync(0xFFFFFFFFu, u, o);
        if (threadIdx.x == 0) g_bsum[blockIdx.x] = u;
    }
}

// ---------- rowptr: block base = reduce(bsum[0..bid)), then local scan
__global__ void k_rowptr2(int N, int E) {
    __shared__ int s[1024];
    __shared__ int ws[32];
    __shared__ int sbase;
    int t = threadIdx.x;

    int v = (t < blockIdx.x) ? g_bsum[t] : 0;
#pragma unroll
    for (int o = 16; o; o >>= 1) v += __shfl_down_sync(0xFFFFFFFFu, v, o);
    if ((t & 31) == 0) ws[t >> 5] = v;
    __syncthreads();
    if (t < 32) {
        int u = ws[t];
#pragma unroll
        for (int o = 16; o; o >>= 1) u += __shfl_down_sync(0xFFFFFFFFu, u, o);
        if (t == 0) sbase = u;
    }

    int i = blockIdx.x * 1024 + t;
    int d = (i < N) ? g_degi[i] : 0;
    s[t] = d;
    __syncthreads();
    for (int off = 1; off < 1024; off <<= 1) {
        int u = (t >= off) ? s[t - off] : 0;
        __syncthreads();
        s[t] += u;
        __syncthreads();
    }
    if (i < N) {
        int excl = sbase + s[t] - d;
        g_rowptr[i] = excl;
        g_next[i]   = excl;
    }
    if (blockIdx.x == 0 && t == 0) g_rowptr[N] = E;
}

// ----------------------------------------------------- scatter into CSR
__global__ void k_scatter(const int* __restrict__ ei, int E) {
    int e = blockIdx.x * blockDim.x + threadIdx.x;
    if (e >= E) return;
    int src = ei[e];
    int dst = ei[(size_t)E + e];
    int pos = atomicAdd(&g_next[dst], 1);
    g_sedge[pos] = make_int4(src, e, dst, 0);
}

// ------------------------------------------------- node precompute layer 1
__global__ void k_node1(const float* __restrict__ x,
                        const float* __restrict__ wn1, const float* __restrict__ bn1,
                        const float* __restrict__ we1, int N) {
    __shared__ float swn[48], sbn[16], sA[256], sB[256];
    for (int i = threadIdx.x; i < 48; i += blockDim.x) swn[i] = wn1[i];
    for (int i = threadIdx.x; i < 16; i += blockDim.x) sbn[i] = bn1[i];
    for (int i = threadIdx.x; i < 256; i += blockDim.x) {
        sA[i] = we1[i];
        sB[i] = we1[304 + i];
    }
    __syncthreads();
    int n = blockIdx.x * blockDim.x + threadIdx.x;
    if (n >= N) return;

    float x0 = x[(size_t)n*3], x1 = x[(size_t)n*3+1], x2 = x[(size_t)n*3+2];
    float dis = rsqrtf((float)g_degi[n]);
    g_dis[n] = dis;

    float h[16];
#pragma unroll
    for (int k = 0; k < 16; k++)
        h[k] = sbn[k] + x0*swn[k] + x1*swn[16+k] + x2*swn[32+k];

    float4* Y = &g_y[(size_t)n*4];
#pragma unroll
    for (int q = 0; q < 4; q++)
        Y[q] = make_float4(dis*h[4*q], dis*h[4*q+1], dis*h[4*q+2], dis*h[4*q+3]);

    float a[16], b[16];
#pragma unroll
    for (int k = 0; k < 16; k++) { a[k] = 0.f; b[k] = 0.f; }
#pragma unroll
    for (int j = 0; j < 16; j++)
#pragma unroll
        for (int k = 0; k < 16; k++) {
            a[k] += h[j] * sA[j*16+k];
            b[k] += h[j] * sB[j*16+k];
        }
    float4* A = &g_A1[(size_t)n*4];
    float4* B = &g_B1[(size_t)n*4];
#pragma unroll
    for (int q = 0; q < 4; q++) {
        A[q] = make_float4(a[4*q], a[4*q+1], a[4*q+2], a[4*q+3]);
        B[q] = make_float4(b[4*q], b[4*q+1], b[4*q+2], b[4*q+3]);
    }
}

// ---------- fused: quad CSR-gather (layer1) + PARALLEL node2 transform
// phase 1: quad-per-node gather (unchanged).
// phase 2: ALL 256 threads — 4 threads/node, lane ch owns channels 4ch..4ch+3.
__global__ void k_agg_node2(const float* __restrict__ wn2, const float* __restrict__ bn2,
                            const float* __restrict__ we2, int N) {
    __shared__ __align__(16) float sw[256];
    __shared__ __align__(16) float sA[256];
    __shared__ __align__(16) float sB[256];
    __shared__ float sbn[16];
    __shared__ float sagg[64 * 17];
    for (int i = threadIdx.x; i < 16; i += blockDim.x) sbn[i] = bn2[i];
    for (int i = threadIdx.x; i < 256; i += blockDim.x) {
        sw[i] = wn2[i];
        sA[i] = we2[i];
        sB[i] = we2[512 + i];
    }
    __syncthreads();

    int t = threadIdx.x;
    int lane = t & 3, q = t >> 2;
    int n = blockIdx.x * 64 + q;

    float4 acc = make_float4(0.f, 0.f, 0.f, 0.f);
    if (n < N) {
        int s  = g_rowptr[n];
        int en = g_rowptr[n + 1];
#pragma unroll 4
        for (int p = s; p < en; p++) {
            int src = g_sedge[p].x;
            float4 v = g_y[(size_t)src * 4 + lane];
            acc.x += v.x; acc.y += v.y; acc.z += v.z; acc.w += v.w;
        }
    }
    float* sg = &sagg[q * 17 + lane * 4];
    sg[0] = acc.x; sg[1] = acc.y; sg[2] = acc.z; sg[3] = acc.w;
    __syncthreads();

    // phase 2: 4 threads per node (same n as phase 1)
    if (n >= N) return;
    float dis = g_dis[n];
    const float* ag = &sagg[q * 17];
    float h[16];
#pragma unroll
    for (int k = 0; k < 16; k++) h[k] = relu(dis * ag[k]);

    int kb = lane * 4;
    float4 bn = *(const float4*)&sbn[kb];
    float v0 = bn.x, v1 = bn.y, v2 = bn.z, v3 = bn.w;
    float a0 = 0.f, a1 = 0.f, a2 = 0.f, a3 = 0.f;
    float b0 = 0.f, b1 = 0.f, b2 = 0.f, b3 = 0.f;
#pragma unroll
    for (int j = 0; j < 16; j++) {
        float hj = h[j];
        float4 w = *(const float4*)&sw[j*16 + kb];
        v0 += hj*w.x; v1 += hj*w.y; v2 += hj*w.z; v3 += hj*w.w;
    }
#pragma unroll
    for (int j = 0; j < 16; j++) {
        float vj = (j < 4)  ? (j==0?v0:j==1?v1:j==2?v2:v3) : 0.f;
        // need full v vector across lanes for A2/B2 — broadcast via quad shuffle
        (void)vj;
    }
    // gather full v[16] across the quad via shuffles
    float vfull[16];
    {
        float mine[4] = {v0, v1, v2, v3};
#pragma unroll
        for (int srcl = 0; srcl < 4; srcl++) {
#pragma unroll
            for (int i = 0; i < 4; i++)
                vfull[srcl*4 + i] = __shfl_sync(0xFFFFFFFFu, mine[i], srcl, 4);
        }
    }
    // y2 write (lane's own 4 channels)
    g_y2[(size_t)n*4 + lane] = make_float4(dis*v0, dis*v1, dis*v2, dis*v3);

#pragma unroll
    for (int j = 0; j < 16; j++) {
        float vj = vfull[j];
        float4 wa = *(const float4*)&sA[j*16 + kb];
        float4 wb = *(const float4*)&sB[j*16 + kb];
        a0 += vj*wa.x; a1 += vj*wa.y; a2 += vj*wa.z; a3 += vj*wa.w;
        b0 += vj*wb.x; b1 += vj*wb.y; b2 += vj*wb.z; b3 += vj*wb.w;
    }
    g_A2[(size_t)n*4 + lane] = make_float4(a0, a1, a2, a3);
    g_B2[(size_t)n*4 + lane] = make_float4(b0, b1, b2, b3);
}

// ---------- fused: quad CSR-gather (layer2) + PARALLEL node output MLP
__global__ void k_agg_node3(const float* __restrict__ wnn1, const float* __restrict__ bnn1,
                            const float* __restrict__ wnn2, const float* __restrict__ bnn2,
                            float* __restrict__ out_node, int N) {
    __shared__ __align__(16) float sw1[256];
    __shared__ float sb1[16], sw2[48], sb2[3];
    __shared__ float sagg[64 * 17];
    for (int i = threadIdx.x; i < 256; i += blockDim.x) sw1[i] = wnn1[i];
    for (int i = threadIdx.x; i < 48;  i += blockDim.x) sw2[i] = wnn2[i];
    for (int i = threadIdx.x; i < 16;  i += blockDim.x) sb1[i] = bnn1[i];
    if (threadIdx.x < 3) sb2[threadIdx.x] = bnn2[threadIdx.x];
    __syncthreads();

    int t = threadIdx.x;
    int lane = t & 3, q = t >> 2;
    int n = blockIdx.x * 64 + q;

    float4 acc = make_float4(0.f, 0.f, 0.f, 0.f);
    if (n < N) {
        int s  = g_rowptr[n];
        int en = g_rowptr[n + 1];
#pragma unroll 4
        for (int p = s; p < en; p++) {
            int src = g_sedge[p].x;
            float4 v = g_y2[(size_t)src * 4 + lane];
            acc.x += v.x; acc.y += v.y; acc.z += v.z; acc.w += v.w;
        }
    }
    float* sg = &sagg[q * 17 + lane * 4];
    sg[0] = acc.x; sg[1] = acc.y; sg[2] = acc.z; sg[3] = acc.w;
    __syncthreads();

    // phase 2: 4 threads per node
    if (n >= N) return;
    float dis = g_dis[n];
    const float* ag = &sagg[q * 17];
    float h[16];
#pragma unroll
    for (int k = 0; k < 16; k++) h[k] = relu(dis * ag[k]);

    int kb = lane * 4;
    float4 bb = *(const float4*)&sb1[kb];
    float t0 = bb.x, t1 = bb.y, t2 = bb.z, t3 = bb.w;
#pragma unroll
    for (int j = 0; j < 16; j++) {
        float hj = h[j];
        float4 w = *(const float4*)&sw1[j*16 + kb];
        t0 += hj*w.x; t1 += hj*w.y; t2 += hj*w.z; t3 += hj*w.w;
    }
    // o = relu(t) @ wen2 — partial over this lane's 4 j's, quad reduce
    float o0 = 0.f, o1 = 0.f, o2 = 0.f;
    float tl[4] = {t0, t1, t2, t3};
#pragma unroll
    for (int i = 0; i < 4; i++) {
        float tj = relu(tl[i]);
        int j = kb + i;
        o0 += tj * sw2[j*3    ];
        o1 += tj * sw2[j*3 + 1];
        o2 += tj * sw2[j*3 + 2];
    }
    o0 += __shfl_xor_sync(0xFFFFFFFFu, o0, 1, 4);
    o0 += __shfl_xor_sync(0xFFFFFFFFu, o0, 2, 4);
    o1 += __shfl_xor_sync(0xFFFFFFFFu, o1, 1, 4);
    o1 += __shfl_xor_sync(0xFFFFFFFFu, o1, 2, 4);
    o2 += __shfl_xor_sync(0xFFFFFFFFu, o2, 1, 4);
    o2 += __shfl_xor_sync(0xFFFFFFFFu, o2, 2, 4);

    if (lane < 3) {
        float val = (lane == 0) ? (o0 + sb2[0]) : (lane == 1) ? (o1 + sb2[1]) : (o2 + sb2[2]);
        out_node[(size_t)n*3 + lane] = val;
    }
}

// ------- layer-2 edge kernel, CSR order, TWO edges per thread
__global__ void __launch_bounds__(256) k_edge2c(
                         const float* __restrict__ ea,
                         const float* __restrict__ we1, const float* __restrict__ be1,
                         const float* __restrict__ we2, const float* __restrict__ be2,
                         const float* __restrict__ wen1, const float* __restrict__ ben1,
                         const float* __restrict__ wen2, const float* __restrict__ ben2,
                         float* __restrict__ out_edge, int E) {
    __shared__ float sm1[48], sbe1[16], sbe2[16], sb1[16], sw2[48], sb2[3];
    __shared__ __align__(16) float sm2[256];
    __shared__ __align__(16) float sw1[256];
    for (int i = threadIdx.x; i < 48; i += blockDim.x) {
        sm1[i] = we1[256 + i];
        sw2[i] = wen2[i];
    }
    for (int i = threadIdx.x; i < 256; i += blockDim.x) {
        sm2[i] = we2[256 + i];
        sw1[i] = wen1[i];
    }
    for (int i = threadIdx.x; i < 16; i += blockDim.x) {
        sbe1[i] = be1[i]; sbe2[i] = be2[i]; sb1[i] = ben1[i];
    }
    if (threadIdx.x < 3) sb2[threadIdx.x] = ben2[threadIdx.x];
    __syncthreads();

    int base = blockIdx.x * 512;
    int p0 = base + threadIdx.x;
    int p1 = p0 + 256;
    bool v0 = p0 < E, v1 = p1 < E;
    int4 r0 = v0 ? g_sedge[p0] : make_int4(0, 0, 0, 0);
    int4 r1 = v1 ? g_sedge[p1] : make_int4(0, 0, 0, 0);

    float ea0a = ea[(size_t)r0.y*3], ea1a = ea[(size_t)r0.y*3+1], ea2a = ea[(size_t)r0.y*3+2];
    float ea0b = ea[(size_t)r1.y*3], ea1b = ea[(size_t)r1.y*3+1], ea2b = ea[(size_t)r1.y*3+2];

    float e1a[16], e1b[16];
    {
        const float4* Aa = &g_A1[(size_t)r0.x*4];
        const float4* Ba = &g_B1[(size_t)r0.z*4];
        const float4* Ab = &g_A1[(size_t)r1.x*4];
        const float4* Bb = &g_B1[(size_t)r1.z*4];
#pragma unroll
        for (int q = 0; q < 4; q++) {
            float4 ta = Aa[q], tb = Ba[q];
            float4 tc = Ab[q], td = Bb[q];
            int k = 4*q;
#pragma unroll
            for (int i = 0; i < 4; i++) {
                float wa = sm1[k+i], wb = sm1[16+k+i], wc = sm1[32+k+i], bbi = sbe1[k+i];
                float sa = (i==0?ta.x:i==1?ta.y:i==2?ta.z:ta.w) + (i==0?tb.x:i==1?tb.y:i==2?tb.z:tb.w);
                float sb = (i==0?tc.x:i==1?tc.y:i==2?tc.z:tc.w) + (i==0?td.x:i==1?td.y:i==2?td.z:td.w);
                e1a[k+i] = relu(sa + bbi + ea0a*wa + ea1a*wb + ea2a*wc);
                e1b[k+i] = relu(sb + bbi + ea0b*wa + ea1b*wb + ea2b*wc);
            }
        }
    }

    float e2a[16], e2b[16];
    {
        u64 acca[8], accb[8];
        const float4* Aa = &g_A2[(size_t)r0.x*4];
        const float4* Ba = &g_B2[(size_t)r0.z*4];
        const float4* Ab = &g_A2[(size_t)r1.x*4];
        const float4* Bb = &g_B2[(size_t)r1.z*4];
#pragma unroll
        for (int q = 0; q < 4; q++) {
            float4 ta = Aa[q], tb = Ba[q];
            float4 tc = Ab[q], td = Bb[q];
            acca[2*q  ] = pack2(ta.x + tb.x + sbe2[4*q  ], ta.y + tb.y + sbe2[4*q+1]);
            acca[2*q+1] = pack2(ta.z + tb.z + sbe2[4*q+2], ta.w + tb.w + sbe2[4*q+3]);
            accb[2*q  ] = pack2(tc.x + td.x + sbe2[4*q  ], tc.y + td.y + sbe2[4*q+1]);
            accb[2*q+1] = pack2(tc.z + td.z + sbe2[4*q+2], tc.w + td.w + sbe2[4*q+3]);
        }
        const u64* W = (const u64*)sm2;
#pragma unroll
        for (int j = 0; j < 16; j++) {
            u64 eja = pack2(e1a[j], e1a[j]);
            u64 ejb = pack2(e1b[j], e1b[j]);
#pragma unroll
            for (int kk = 0; kk < 8; kk++) {
                u64 w = W[j*8 + kk];
                acca[kk] = ffma2(eja, w, acca[kk]);
                accb[kk] = ffma2(ejb, w, accb[kk]);
            }
        }
#pragma unroll
        for (int kk = 0; kk < 8; kk++) {
            float2 fa = unpack2(acca[kk]);
            float2 fb = unpack2(accb[kk]);
            e2a[2*kk] = relu(fa.x); e2a[2*kk+1] = relu(fa.y);
            e2b[2*kk] = relu(fb.x); e2b[2*kk+1] = relu(fb.y);
        }
    }

    float tva[16], tvb[16];
    {
        u64 acca[8], accb[8];
#pragma unroll
        for (int kk = 0; kk < 8; kk++) {
            u64 b = pack2(sb1[2*kk], sb1[2*kk+1]);
            acca[kk] = b; accb[kk] = b;
        }
        const u64* W = (const u64*)sw1;
#pragma unroll
        for (int j = 0; j < 16; j++) {
            u64 eja = pack2(e2a[j], e2a[j]);
            u64 ejb = pack2(e2b[j], e2b[j]);
#pragma unroll
            for (int kk = 0; kk < 8; kk++) {
                u64 w = W[j*8 + kk];
                acca[kk] = ffma2(eja, w, acca[kk]);
                accb[kk] = ffma2(ejb, w, accb[kk]);
            }
        }
#pragma unroll
        for (int kk = 0; kk < 8; kk++) {
            float2 fa = unpack2(acca[kk]);
            float2 fb = unpack2(accb[kk]);
            tva[2*kk] = fa.x; tva[2*kk+1] = fa.y;
            tvb[2*kk] = fb.x; tvb[2*kk+1] = fb.y;
        }
    }

    float o0a = sb2[0], o1a = sb2[1], o2a = sb2[2];
    float o0b = sb2[0], o1b = sb2[1], o2b = sb2[2];
#pragma unroll
    for (int j = 0; j < 16; j++) {
        float w0 = sw2[j*3], w1 = sw2[j*3+1], w2 = sw2[j*3+2];
        float ta = relu(tva[j]);
        float tb = relu(tvb[j]);
        o0a += ta * w0; o1a += ta * w1; o2a += ta * w2;
        o0b += tb * w0; o1b += tb * w1; o2b += tb * w2;
    }
    if (v0) {
        out_edge[(size_t)r0.y*3    ] = o0a;
        out_edge[(size_t)r0.y*3 + 1] = o1a;
        out_edge[(size_t)r0.y*3 + 2] = o2a;
    }
    if (v1) {
        out_edge[(size_t)r1.y*3    ] = o0b;
        out_edge[(size_t)r1.y*3 + 1] = o1b;
        out_edge[(size_t)r1.y*3 + 2] = o2b;
    }
}

extern "C" void kernel_launch(void* const* d_in, const int* in_sizes, int n_in,
                              void* d_out, int out_size) {
    const float* x    = (const float*)d_in[0];
    const float* ea   = (const float*)d_in[1];
    const int*   ei   = (const int*)d_in[2];      // int32 (JAX x64 disabled)
    const float *wn1 = (const float*)d_in[3],  *bn1 = (const float*)d_in[4];
    const float *we1 = (const float*)d_in[5],  *be1 = (const float*)d_in[6];
    const float *wn2 = (const float*)d_in[7],  *bn2 = (const float*)d_in[8];
    const float *we2 = (const float*)d_in[9],  *be2 = (const float*)d_in[10];
    const float *wnn1= (const float*)d_in[11], *bnn1= (const float*)d_in[12];
    const float *wnn2= (const float*)d_in[13], *bnn2= (const float*)d_in[14];
    const float *wen1= (const float*)d_in[15], *ben1= (const float*)d_in[16];
    const float *wen2= (const float*)d_in[17], *ben2= (const float*)d_in[18];

    int N = in_sizes[0] / 3;
    int E = in_sizes[1] / 3;
    float* out_node = (float*)d_out;
    float* out_edge = out_node + (size_t)N * 3;

    void* pdegi;
    cudaGetSymbolAddress(&pdegi, g_degi);
    cudaMemsetAsync(pdegi, 0, (size_t)N * sizeof(int));

    const int TB = 256;
    int gbE   = (E + TB - 1) / TB;
    int gbE2  = (E + 511) / 512;
    int gbN   = (N + TB - 1) / TB;
    int gbN64 = (N + 63) / 64;
    int NB    = (N + 1023) / 1024;

    k_deg      <<<gbE,  TB>>>(ei, E);
    k_bsum     <<<NB, 1024>>>(N);
    k_rowptr2  <<<NB, 1024>>>(N, E);
    k_scatter  <<<gbE,  TB>>>(ei, E);            // slot 4 (profiled)
    k_node1    <<<gbN,  TB>>>(x, wn1, bn1, we1, N);
    k_agg_node2<<<gbN64, TB>>>(wn2, bn2, we2, N);
    k_edge2c   <<<gbE2, TB>>>(ea, we1, be1, we2, be2, wen1, ben1, wen2, ben2,
                              out_edge, E);
    k_agg_node3<<<gbN64, TB>>>(wnn1, bnn1, wnn2, bnn2, out_node, N);
}

// round 13
// speedup vs baseline: 1.2385x; 1.0575x over previous
#include <cuda_runtime.h>

#define NMAX 100000
#define EMAX 3200000

typedef unsigned long long u64;

// scratch (all __device__ globals; no allocation anywhere)
__device__ int    g_degi  [NMAX];
__device__ int    g_rowptr[NMAX + 1];
__device__ int    g_next  [NMAX];
__device__ int    g_bsum  [128];
__device__ int4   g_sedge [EMAX];     // (src, eid, dst, 0) sorted by dst
__device__ float  g_dis   [NMAX];
__device__ float4 g_y     [NMAX * 4];
__device__ float4 g_y2    [NMAX * 4];
__device__ float4 g_A1    [NMAX * 4];
__device__ float4 g_B1    [NMAX * 4];
__device__ float4 g_A2    [NMAX * 4];
__device__ float4 g_B2    [NMAX * 4];

__device__ __forceinline__ float relu(float v) { return fmaxf(v, 0.0f); }

__device__ __forceinline__ u64 pack2(float lo, float hi) {
    u64 r; asm("mov.b64 %0, {%1, %2};" : "=l"(r) : "f"(lo), "f"(hi)); return r;
}
__device__ __forceinline__ u64 ffma2(u64 a, u64 b, u64 c) {
    u64 d; asm("fma.rn.f32x2 %0, %1, %2, %3;" : "=l"(d) : "l"(a), "l"(b), "l"(c)); return d;
}
__device__ __forceinline__ float2 unpack2(u64 v) {
    float2 f; asm("mov.b64 {%0, %1}, %2;" : "=f"(f.x), "=f"(f.y) : "l"(v)); return f;
}

// ---------------------------------------------------------------- degree
__global__ void k_deg(const int* __restrict__ ei, int E) {
    int e = blockIdx.x * blockDim.x + threadIdx.x;
    if (e < E) atomicAdd(&g_degi[ei[(size_t)E + e]], 1);
}

// -------------------------------------------- per-1024-chunk block sums
__global__ void k_bsum(int N) {
    int i = blockIdx.x * 1024 + threadIdx.x;
    int v = (i < N) ? g_degi[i] : 0;
#pragma unroll
    for (int o = 16; o; o >>= 1) v += __shfl_down_sync(0xFFFFFFFFu, v, o);
    __shared__ int ws[32];
    if ((threadIdx.x & 31) == 0) ws[threadIdx.x >> 5] = v;
    __syncthreads();
    if (threadIdx.x < 32) {
        int u = ws[threadIdx.x];
#pragma unroll
        for (int o = 16; o; o >>= 1) u += __shfl_down_sync(0xFFFFFFFFu, u, o);
        if (threadIdx.x == 0) g_bsum[blockIdx.x] = u;
    }
}

// ---------- rowptr: block base = reduce(bsum[0..bid)), then local scan
__global__ void k_rowptr2(int N, int E) {
    __shared__ int s[1024];
    __shared__ int ws[32];
    __shared__ int sbase;
    int t = threadIdx.x;

    int v = (t < blockIdx.x) ? g_bsum[t] : 0;
#pragma unroll
    for (int o = 16; o; o >>= 1) v += __shfl_down_sync(0xFFFFFFFFu, v, o);
    if ((t & 31) == 0) ws[t >> 5] = v;
    __syncthreads();
    if (t < 32) {
        int u = ws[t];
#pragma unroll
        for (int o = 16; o; o >>= 1) u += __shfl_down_sync(0xFFFFFFFFu, u, o);
        if (t == 0) sbase = u;
    }

    int i = blockIdx.x * 1024 + t;
    int d = (i < N) ? g_degi[i] : 0;
    s[t] = d;
    __syncthreads();
    for (int off = 1; off < 1024; off <<= 1) {
        int u = (t >= off) ? s[t - off] : 0;
        __syncthreads();
        s[t] += u;
        __syncthreads();
    }
    if (i < N) {
        int excl = sbase + s[t] - d;
        g_rowptr[i] = excl;
        g_next[i]   = excl;
    }
    if (blockIdx.x == 0 && t == 0) g_rowptr[N] = E;
}

// ----------------------------------------------------- scatter into CSR
__global__ void k_scatter(const int* __restrict__ ei, int E) {
    int e = blockIdx.x * blockDim.x + threadIdx.x;
    if (e >= E) return;
    int src = ei[e];
    int dst = ei[(size_t)E + e];
    int pos = atomicAdd(&g_next[dst], 1);
    g_sedge[pos] = make_int4(src, e, dst, 0);
}

// ------------------------------------------------- node precompute layer 1
__global__ void k_node1(const float* __restrict__ x,
                        const float* __restrict__ wn1, const float* __restrict__ bn1,
                        const float* __restrict__ we1, int N) {
    __shared__ float swn[48], sbn[16], sA[256], sB[256];
    for (int i = threadIdx.x; i < 48; i += blockDim.x) swn[i] = wn1[i];
    for (int i = threadIdx.x; i < 16; i += blockDim.x) sbn[i] = bn1[i];
    for (int i = threadIdx.x; i < 256; i += blockDim.x) {
        sA[i] = we1[i];
        sB[i] = we1[304 + i];
    }
    __syncthreads();
    int n = blockIdx.x * blockDim.x + threadIdx.x;
    if (n >= N) return;

    float x0 = x[(size_t)n*3], x1 = x[(size_t)n*3+1], x2 = x[(size_t)n*3+2];
    float dis = rsqrtf((float)g_degi[n]);
    g_dis[n] = dis;

    float h[16];
#pragma unroll
    for (int k = 0; k < 16; k++)
        h[k] = sbn[k] + x0*swn[k] + x1*swn[16+k] + x2*swn[32+k];

    float4* Y = &g_y[(size_t)n*4];
#pragma unroll
    for (int q = 0; q < 4; q++)
        Y[q] = make_float4(dis*h[4*q], dis*h[4*q+1], dis*h[4*q+2], dis*h[4*q+3]);

    float a[16], b[16];
#pragma unroll
    for (int k = 0; k < 16; k++) { a[k] = 0.f; b[k] = 0.f; }
#pragma unroll
    for (int j = 0; j < 16; j++)
#pragma unroll
        for (int k = 0; k < 16; k++) {
            a[k] += h[j] * sA[j*16+k];
            b[k] += h[j] * sB[j*16+k];
        }
    float4* A = &g_A1[(size_t)n*4];
    float4* B = &g_B1[(size_t)n*4];
#pragma unroll
    for (int q = 0; q < 4; q++) {
        A[q] = make_float4(a[4*q], a[4*q+1], a[4*q+2], a[4*q+3]);
        B[q] = make_float4(b[4*q], b[4*q+1], b[4*q+2], b[4*q+3]);
    }
}

// ---------- fused: quad CSR-gather (layer1) + PARALLEL node2 transform
__global__ void k_agg_node2(const float* __restrict__ wn2, const float* __restrict__ bn2,
                            const float* __restrict__ we2, int N) {
    __shared__ __align__(16) float sw[256];
    __shared__ __align__(16) float sA[256];
    __shared__ __align__(16) float sB[256];
    __shared__ float sbn[16];
    __shared__ float sagg[64 * 17];
    for (int i = threadIdx.x; i < 16; i += blockDim.x) sbn[i] = bn2[i];
    for (int i = threadIdx.x; i < 256; i += blockDim.x) {
        sw[i] = wn2[i];
        sA[i] = we2[i];
        sB[i] = we2[512 + i];
    }
    __syncthreads();

    int t = threadIdx.x;
    int lane = t & 3, q = t >> 2;
    int n = blockIdx.x * 64 + q;

    float4 acc = make_float4(0.f, 0.f, 0.f, 0.f);
    if (n < N) {
        int s  = g_rowptr[n];
        int en = g_rowptr[n + 1];
#pragma unroll 4
        for (int p = s; p < en; p++) {
            int src = g_sedge[p].x;
            float4 v = g_y[(size_t)src * 4 + lane];
            acc.x += v.x; acc.y += v.y; acc.z += v.z; acc.w += v.w;
        }
    }
    float* sg = &sagg[q * 17 + lane * 4];
    sg[0] = acc.x; sg[1] = acc.y; sg[2] = acc.z; sg[3] = acc.w;
    __syncthreads();

    if (n >= N) return;
    float dis = g_dis[n];
    const float* ag = &sagg[q * 17];
    float h[16];
#pragma unroll
    for (int k = 0; k < 16; k++) h[k] = relu(dis * ag[k]);

    int kb = lane * 4;
    float4 bn = *(const float4*)&sbn[kb];
    float v0 = bn.x, v1 = bn.y, v2 = bn.z, v3 = bn.w;
    float a0 = 0.f, a1 = 0.f, a2 = 0.f, a3 = 0.f;
    float b0 = 0.f, b1 = 0.f, b2 = 0.f, b3 = 0.f;
#pragma unroll
    for (int j = 0; j < 16; j++) {
        float hj = h[j];
        float4 w = *(const float4*)&sw[j*16 + kb];
        v0 += hj*w.x; v1 += hj*w.y; v2 += hj*w.z; v3 += hj*w.w;
    }
    float vfull[16];
    {
        float mine[4] = {v0, v1, v2, v3};
#pragma unroll
        for (int srcl = 0; srcl < 4; srcl++) {
#pragma unroll
            for (int i = 0; i < 4; i++)
                vfull[srcl*4 + i] = __shfl_sync(0xFFFFFFFFu, mine[i], srcl, 4);
        }
    }
    g_y2[(size_t)n*4 + lane] = make_float4(dis*v0, dis*v1, dis*v2, dis*v3);

#pragma unroll
    for (int j = 0; j < 16; j++) {
        float vj = vfull[j];
        float4 wa = *(const float4*)&sA[j*16 + kb];
        float4 wb = *(const float4*)&sB[j*16 + kb];
        a0 += vj*wa.x; a1 += vj*wa.y; a2 += vj*wa.z; a3 += vj*wa.w;
        b0 += vj*wb.x; b1 += vj*wb.y; b2 += vj*wb.z; b3 += vj*wb.w;
    }
    g_A2[(size_t)n*4 + lane] = make_float4(a0, a1, a2, a3);
    g_B2[(size_t)n*4 + lane] = make_float4(b0, b1, b2, b3);
}

// ---------- fused: quad CSR-gather (layer2) + PARALLEL node output MLP
__global__ void k_agg_node3(const float* __restrict__ wnn1, const float* __restrict__ bnn1,
                            const float* __restrict__ wnn2, const float* __restrict__ bnn2,
                            float* __restrict__ out_node, int N) {
    __shared__ __align__(16) float sw1[256];
    __shared__ float sb1[16], sw2[48], sb2[3];
    __shared__ float sagg[64 * 17];
    for (int i = threadIdx.x; i < 256; i += blockDim.x) sw1[i] = wnn1[i];
    for (int i = threadIdx.x; i < 48;  i += blockDim.x) sw2[i] = wnn2[i];
    for (int i = threadIdx.x; i < 16;  i += blockDim.x) sb1[i] = bnn1[i];
    if (threadIdx.x < 3) sb2[threadIdx.x] = bnn2[threadIdx.x];
    __syncthreads();

    int t = threadIdx.x;
    int lane = t & 3, q = t >> 2;
    int n = blockIdx.x * 64 + q;

    float4 acc = make_float4(0.f, 0.f, 0.f, 0.f);
    if (n < N) {
        int s  = g_rowptr[n];
        int en = g_rowptr[n + 1];
#pragma unroll 4
        for (int p = s; p < en; p++) {
            int src = g_sedge[p].x;
            float4 v = g_y2[(size_t)src * 4 + lane];
            acc.x += v.x; acc.y += v.y; acc.z += v.z; acc.w += v.w;
        }
    }
    float* sg = &sagg[q * 17 + lane * 4];
    sg[0] = acc.x; sg[1] = acc.y; sg[2] = acc.z; sg[3] = acc.w;
    __syncthreads();

    if (n >= N) return;
    float dis = g_dis[n];
    const float* ag = &sagg[q * 17];
    float h[16];
#pragma unroll
    for (int k = 0; k < 16; k++) h[k] = relu(dis * ag[k]);

    int kb = lane * 4;
    float4 bb = *(const float4*)&sb1[kb];
    float t0 = bb.x, t1 = bb.y, t2 = bb.z, t3 = bb.w;
#pragma unroll
    for (int j = 0; j < 16; j++) {
        float hj = h[j];
        float4 w = *(const float4*)&sw1[j*16 + kb];
        t0 += hj*w.x; t1 += hj*w.y; t2 += hj*w.z; t3 += hj*w.w;
    }
    float o0 = 0.f, o1 = 0.f, o2 = 0.f;
    float tl[4] = {t0, t1, t2, t3};
#pragma unroll
    for (int i = 0; i < 4; i++) {
        float tj = relu(tl[i]);
        int j = kb + i;
        o0 += tj * sw2[j*3    ];
        o1 += tj * sw2[j*3 + 1];
        o2 += tj * sw2[j*3 + 2];
    }
    o0 += __shfl_xor_sync(0xFFFFFFFFu, o0, 1, 4);
    o0 += __shfl_xor_sync(0xFFFFFFFFu, o0, 2, 4);
    o1 += __shfl_xor_sync(0xFFFFFFFFu, o1, 1, 4);
    o1 += __shfl_xor_sync(0xFFFFFFFFu, o1, 2, 4);
    o2 += __shfl_xor_sync(0xFFFFFFFFu, o2, 1, 4);
    o2 += __shfl_xor_sync(0xFFFFFFFFu, o2, 2, 4);

    if (lane < 3) {
        float val = (lane == 0) ? (o0 + sb2[0]) : (lane == 1) ? (o1 + sb2[1]) : (o2 + sb2[2]);
        out_node[(size_t)n*3 + lane] = val;
    }
}

// ------- layer-2 edge kernel, CSR order, TWO edges per thread
__global__ void __launch_bounds__(256) k_edge2c(
                         const float* __restrict__ ea,
                         const float* __restrict__ we1, const float* __restrict__ be1,
                         const float* __restrict__ we2, const float* __restrict__ be2,
                         const float* __restrict__ wen1, const float* __restrict__ ben1,
                         const float* __restrict__ wen2, const float* __restrict__ ben2,
                         float* __restrict__ out_edge, int E) {
    __shared__ float sm1[48], sbe1[16], sbe2[16], sb1[16], sw2[48], sb2[3];
    __shared__ __align__(16) float sm2[256];
    __shared__ __align__(16) float sw1[256];
    for (int i = threadIdx.x; i < 48; i += blockDim.x) {
        sm1[i] = we1[256 + i];
        sw2[i] = wen2[i];
    }
    for (int i = threadIdx.x; i < 256; i += blockDim.x) {
        sm2[i] = we2[256 + i];
        sw1[i] = wen1[i];
    }
    for (int i = threadIdx.x; i < 16; i += blockDim.x) {
        sbe1[i] = be1[i]; sbe2[i] = be2[i]; sb1[i] = ben1[i];
    }
    if (threadIdx.x < 3) sb2[threadIdx.x] = ben2[threadIdx.x];
    __syncthreads();

    int base = blockIdx.x * 512;
    int p0 = base + threadIdx.x;
    int p1 = p0 + 256;
    bool v0 = p0 < E, v1 = p1 < E;
    int4 r0 = v0 ? g_sedge[p0] : make_int4(0, 0, 0, 0);
    int4 r1 = v1 ? g_sedge[p1] : make_int4(0, 0, 0, 0);

    float ea0a = ea[(size_t)r0.y*3], ea1a = ea[(size_t)r0.y*3+1], ea2a = ea[(size_t)r0.y*3+2];
    float ea0b = ea[(size_t)r1.y*3], ea1b = ea[(size_t)r1.y*3+1], ea2b = ea[(size_t)r1.y*3+2];

    float e1a[16], e1b[16];
    {
        const float4* Aa = &g_A1[(size_t)r0.x*4];
        const float4* Ba = &g_B1[(size_t)r0.z*4];
        const float4* Ab = &g_A1[(size_t)r1.x*4];
        const float4* Bb = &g_B1[(size_t)r1.z*4];
#pragma unroll
        for (int q = 0; q < 4; q++) {
            float4 ta = Aa[q], tb = Ba[q];
            float4 tc = Ab[q], td = Bb[q];
            int k = 4*q;
#pragma unroll
            for (int i = 0; i < 4; i++) {
                float wa = sm1[k+i], wb = sm1[16+k+i], wc = sm1[32+k+i], bbi = sbe1[k+i];
                float sa = (i==0?ta.x:i==1?ta.y:i==2?ta.z:ta.w) + (i==0?tb.x:i==1?tb.y:i==2?tb.z:tb.w);
                float sb = (i==0?tc.x:i==1?tc.y:i==2?tc.z:tc.w) + (i==0?td.x:i==1?td.y:i==2?td.z:td.w);
                e1a[k+i] = relu(sa + bbi + ea0a*wa + ea1a*wb + ea2a*wc);
                e1b[k+i] = relu(sb + bbi + ea0b*wa + ea1b*wb + ea2b*wc);
            }
        }
    }

    float e2a[16], e2b[16];
    {
        u64 acca[8], accb[8];
        const float4* Aa = &g_A2[(size_t)r0.x*4];
        const float4* Ba = &g_B2[(size_t)r0.z*4];
        const float4* Ab = &g_A2[(size_t)r1.x*4];
        const float4* Bb = &g_B2[(size_t)r1.z*4];
#pragma unroll
        for (int q = 0; q < 4; q++) {
            float4 ta = Aa[q], tb = Ba[q];
            float4 tc = Ab[q], td = Bb[q];
            acca[2*q  ] = pack2(ta.x + tb.x + sbe2[4*q  ], ta.y + tb.y + sbe2[4*q+1]);
            acca[2*q+1] = pack2(ta.z + tb.z + sbe2[4*q+2], ta.w + tb.w + sbe2[4*q+3]);
            accb[2*q  ] = pack2(tc.x + td.x + sbe2[4*q  ], tc.y + td.y + sbe2[4*q+1]);
            accb[2*q+1] = pack2(tc.z + td.z + sbe2[4*q+2], tc.w + td.w + sbe2[4*q+3]);
        }
        const u64* W = (const u64*)sm2;
#pragma unroll
        for (int j = 0; j < 16; j++) {
            u64 eja = pack2(e1a[j], e1a[j]);
            u64 ejb = pack2(e1b[j], e1b[j]);
#pragma unroll
            for (int kk = 0; kk < 8; kk++) {
                u64 w = W[j*8 + kk];
                acca[kk] = ffma2(eja, w, acca[kk]);
                accb[kk] = ffma2(ejb, w, accb[kk]);
            }
        }
#pragma unroll
        for (int kk = 0; kk < 8; kk++) {
            float2 fa = unpack2(acca[kk]);
            float2 fb = unpack2(accb[kk]);
            e2a[2*kk] = relu(fa.x); e2a[2*kk+1] = relu(fa.y);
            e2b[2*kk] = relu(fb.x); e2b[2*kk+1] = relu(fb.y);
        }
    }

    float tva[16], tvb[16];
    {
        u64 acca[8], accb[8];
#pragma unroll
        for (int kk = 0; kk < 8; kk++) {
            u64 b = pack2(sb1[2*kk], sb1[2*kk+1]);
            acca[kk] = b; accb[kk] = b;
        }
        const u64* W = (const u64*)sw1;
#pragma unroll
        for (int j = 0; j < 16; j++) {
            u64 eja = pack2(e2a[j], e2a[j]);
            u64 ejb = pack2(e2b[j], e2b[j]);
#pragma unroll
            for (int kk = 0; kk < 8; kk++) {
                u64 w = W[j*8 + kk];
                acca[kk] = ffma2(eja, w, acca[kk]);
                accb[kk] = ffma2(ejb, w, accb[kk]);
            }
        }
#pragma unroll
        for (int kk = 0; kk < 8; kk++) {
            float2 fa = unpack2(acca[kk]);
            float2 fb = unpack2(accb[kk]);
            tva[2*kk] = fa.x; tva[2*kk+1] = fa.y;
            tvb[2*kk] = fb.x; tvb[2*kk+1] = fb.y;
        }
    }

    float o0a = sb2[0], o1a = sb2[1], o2a = sb2[2];
    float o0b = sb2[0], o1b = sb2[1], o2b = sb2[2];
#pragma unroll
    for (int j = 0; j < 16; j++) {
        float w0 = sw2[j*3], w1 = sw2[j*3+1], w2 = sw2[j*3+2];
        float ta = relu(tva[j]);
        float tb = relu(tvb[j]);
        o0a += ta * w0; o1a += ta * w1; o2a += ta * w2;
        o0b += tb * w0; o1b += tb * w1; o2b += tb * w2;
    }
    if (v0) {
        out_edge[(size_t)r0.y*3    ] = o0a;
        out_edge[(size_t)r0.y*3 + 1] = o1a;
        out_edge[(size_t)r0.y*3 + 2] = o2a;
    }
    if (v1) {
        out_edge[(size_t)r1.y*3    ] = o0b;
        out_edge[(size_t)r1.y*3 + 1] = o1b;
        out_edge[(size_t)r1.y*3 + 2] = o2b;
    }
}

extern "C" void kernel_launch(void* const* d_in, const int* in_sizes, int n_in,
                              void* d_out, int out_size) {
    const float* x    = (const float*)d_in[0];
    const float* ea   = (const float*)d_in[1];
    const int*   ei   = (const int*)d_in[2];      // int32 (JAX x64 disabled)
    const float *wn1 = (const float*)d_in[3],  *bn1 = (const float*)d_in[4];
    const float *we1 = (const float*)d_in[5],  *be1 = (const float*)d_in[6];
    const float *wn2 = (const float*)d_in[7],  *bn2 = (const float*)d_in[8];
    const float *we2 = (const float*)d_in[9],  *be2 = (const float*)d_in[10];
    const float *wnn1= (const float*)d_in[11], *bnn1= (const float*)d_in[12];
    const float *wnn2= (const float*)d_in[13], *bnn2= (const float*)d_in[14];
    const float *wen1= (const float*)d_in[15], *ben1= (const float*)d_in[16];
    const float *wen2= (const float*)d_in[17], *ben2= (const float*)d_in[18];

    int N = in_sizes[0] / 3;
    int E = in_sizes[1] / 3;
    float* out_node = (float*)d_out;
    float* out_edge = out_node + (size_t)N * 3;

    void* pdegi;
    cudaGetSymbolAddress(&pdegi, g_degi);

    const int TB = 256;
    int gbE   = (E + TB - 1) / TB;
    int gbE2  = (E + 511) / 512;
    int gbN   = (N + TB - 1) / TB;
    int gbN64 = (N + 63) / 64;
    int NB    = (N + 1023) / 1024;

    cudaStream_t s1;
    cudaStreamCreateWithFlags(&s1, cudaStreamNonBlocking);
    cudaEvent_t evDeg, evN1, evA2, evN3;
    cudaEventCreateWithFlags(&evDeg, cudaEventDisableTiming);
    cudaEventCreateWithFlags(&evN1,  cudaEventDisableTiming);
    cudaEventCreateWithFlags(&evA2,  cudaEventDisableTiming);
    cudaEventCreateWithFlags(&evN3,  cudaEventDisableTiming);

    cudaMemsetAsync(pdegi, 0, (size_t)N * sizeof(int));

    // main chain on default stream
    k_deg    <<<gbE,  TB>>>(ei, E);
    cudaEventRecord(evDeg, 0);
    k_bsum   <<<NB, 1024>>>(N);
    k_rowptr2<<<NB, 1024>>>(N, E);
    k_scatter<<<gbE,  TB>>>(ei, E);              // 4th kernel (profiled)

    // side stream: node1 overlaps with bsum/rowptr/scatter
    cudaStreamWaitEvent(s1, evDeg, 0);
    k_node1<<<gbN, TB, 0, s1>>>(x, wn1, bn1, we1, N);
    cudaEventRecord(evN1, s1);

    // join: agg_node2 needs scatter (main) + node1 (side)
    cudaStreamWaitEvent(0, evN1, 0);
    k_agg_node2<<<gbN64, TB>>>(wn2, bn2, we2, N);
    cudaEventRecord(evA2, 0);

    // fork: edge2c (main) || agg_node3 (side) — independent of each other
    cudaStreamWaitEvent(s1, evA2, 0);
    k_agg_node3<<<gbN64, TB, 0, s1>>>(wnn1, bnn1, wnn2, bnn2, out_node, N);
    cudaEventRecord(evN3, s1);

    k_edge2c<<<gbE2, TB>>>(ea, we1, be1, we2, be2, wen1, ben1, wen2, ben2,
                           out_edge, E);

    // join back so the capture/launch ends on the default stream
    cudaStreamWaitEvent(0, evN3, 0);

    cudaEventDestroy(evDeg);
    cudaEventDestroy(evN1);
    cudaEventDestroy(evA2);
    cudaEventDestroy(evN3);
    cudaStreamDestroy(s1);
}